// round 4
// baseline (speedup 1.0000x reference)
#include <cuda_runtime.h>

#define Nn 100000
#define Ee 3200000
#define CLIND 64
#define MELD 1280
#define Hd 128
#define Cd 4
#define XCATD 192   // CLIN + H

// ---------------- scratch (device globals; no allocation) ----------------
// g_xcat doubles as the aggregation buffer once the concat features are consumed.
__device__ float g_xcat[(size_t)Nn * XCATD];   // [N,192] then reused: agg [N,128]
__device__ float g_x1[(size_t)Nn * Hd];        // after concat_linear + relu
__device__ float g_x2[(size_t)Nn * Hd];        // after sage1 + relu
__device__ int   g_deg[Nn];
__device__ int   g_rowstart[Nn + 1];
__device__ int   g_cursor[Nn];
__device__ int   g_csr[Ee];
__device__ float g_invdeg[Nn];
__device__ int   g_part[128];
__device__ int   g_edge_first;   // 1 if candidate-0 of the 6.4M pair is edge_index

// ---------------- sniff which 6.4M input is edge_index ----------------
__global__ void k_sniff(const int* __restrict__ c0) {
    __shared__ int ok;
    if (threadIdx.x == 0) ok = 1;
    __syncthreads();
    for (int i = threadIdx.x; i < 4096; i += blockDim.x) {
        unsigned v = (unsigned)c0[i];
        if (v >= (unsigned)Nn) ok = 0;   // float bit patterns land here
    }
    __syncthreads();
    if (threadIdx.x == 0) g_edge_first = ok;
}

// ---------------- graph preprocessing ----------------
__global__ void k_zerodeg() {
    int i = blockIdx.x * blockDim.x + threadIdx.x;
    if (i < Nn) g_deg[i] = 0;
}

__global__ void k_degree(const int* __restrict__ c0, const int* __restrict__ c1) {
    const int* ei = g_edge_first ? c0 : c1;
    int e = blockIdx.x * blockDim.x + threadIdx.x;
    if (e < Ee) {
        unsigned dst = (unsigned)ei[Ee + e];
        if (dst < (unsigned)Nn) atomicAdd(&g_deg[dst], 1);
    }
}

__global__ void k_scan1() {
    __shared__ int s[1024];
    int i = blockIdx.x * 1024 + threadIdx.x;
    int v = (i < Nn) ? g_deg[i] : 0;
    s[threadIdx.x] = v;
    __syncthreads();
    #pragma unroll
    for (int off = 1; off < 1024; off <<= 1) {
        int t = (threadIdx.x >= off) ? s[threadIdx.x - off] : 0;
        __syncthreads();
        s[threadIdx.x] += t;
        __syncthreads();
    }
    if (i < Nn) g_rowstart[i] = s[threadIdx.x] - v;  // block-local exclusive
    if (threadIdx.x == 1023) g_part[blockIdx.x] = s[1023];
}

__global__ void k_scan2(int nb) {
    if (blockIdx.x == 0 && threadIdx.x == 0) {
        int acc = 0;
        for (int b = 0; b < nb; b++) { int t = g_part[b]; g_part[b] = acc; acc += t; }
        g_rowstart[Nn] = acc;
    }
}

__global__ void k_scan3() {
    int i = blockIdx.x * 1024 + threadIdx.x;
    if (i < Nn) {
        g_rowstart[i] += g_part[blockIdx.x];
        g_cursor[i] = 0;
        int d = g_deg[i];
        g_invdeg[i] = 1.0f / (float)(d > 1 ? d : 1);
    }
}

__global__ void k_fill(const int* __restrict__ c0, const int* __restrict__ c1) {
    const int* ei = g_edge_first ? c0 : c1;
    int e = blockIdx.x * blockDim.x + threadIdx.x;
    if (e < Ee) {
        unsigned dst = (unsigned)ei[Ee + e];
        unsigned src = (unsigned)ei[e];
        if (dst < (unsigned)Nn) {
            int pos = atomicAdd(&g_cursor[dst], 1);
            int idx = g_rowstart[dst] + pos;
            if (idx >= 0 && idx < Ee)
                g_csr[idx] = (src < (unsigned)Nn) ? (int)src : 0;
        }
    }
}

// ---------------- clinical copy into xcat cols [0,64) ----------------
__global__ void k_copyclin(const float* __restrict__ c0, const float* __restrict__ c1) {
    const float* clin = g_edge_first ? c1 : c0;
    int u = blockIdx.x * blockDim.x + threadIdx.x;  // N*16 float4s
    if (u < Nn * 16) {
        int row = u >> 4, c = (u & 15) << 2;
        *(float4*)&g_xcat[(size_t)row * XCATD + c] =
            *(const float4*)&clin[(size_t)row * CLIND + c];
    }
}

// ---------------- generic fp32 GEMM: C[:,coloff:coloff+128] (op)= act(A@W^T + b) ----------------
// A [M,K] row-major (lda), W [128,K] row-major, C row-major (ldc).
// Block tile: 64 rows x 128 cols, TK=32, 256 threads, each thread 4x8 outputs.
template <bool RELU, bool ACCUM>
__global__ void k_gemm(const float* __restrict__ A, int lda, int K,
                       const float* __restrict__ W,
                       const float* __restrict__ bias,
                       float* __restrict__ C, int ldc, int coloff, int M)
{
    __shared__ float As[32][68];
    __shared__ float Bs[32][132];
    int tid = threadIdx.x;
    int tx = tid & 15;    // col group: covers cols tx*8..tx*8+7
    int ty = tid >> 4;    // row group: covers rows ty*4..ty*4+3
    int rowBase = blockIdx.x * 64;

    float acc[4][8];
    #pragma unroll
    for (int i = 0; i < 4; i++)
        #pragma unroll
        for (int j = 0; j < 8; j++) acc[i][j] = 0.f;

    for (int k0 = 0; k0 < K; k0 += 32) {
        // load A tile: 64 rows x 32 k  (512 float4s, 2 per thread)
        #pragma unroll
        for (int i = 0; i < 2; i++) {
            int u = tid + i * 256;
            int r = u >> 3, kq = u & 7;
            float4 v = make_float4(0.f, 0.f, 0.f, 0.f);
            int ar = rowBase + r;
            if (ar < M) v = *(const float4*)&A[(size_t)ar * lda + k0 + kq * 4];
            As[kq * 4 + 0][r] = v.x;
            As[kq * 4 + 1][r] = v.y;
            As[kq * 4 + 2][r] = v.z;
            As[kq * 4 + 3][r] = v.w;
        }
        // load W tile: 128 cols x 32 k (1024 float4s, 4 per thread)
        #pragma unroll
        for (int i = 0; i < 4; i++) {
            int u = tid + i * 256;
            int c = u >> 3, kq = u & 7;
            float4 v = *(const float4*)&W[(size_t)c * K + k0 + kq * 4];
            Bs[kq * 4 + 0][c] = v.x;
            Bs[kq * 4 + 1][c] = v.y;
            Bs[kq * 4 + 2][c] = v.z;
            Bs[kq * 4 + 3][c] = v.w;
        }
        __syncthreads();

        #pragma unroll
        for (int k = 0; k < 32; k++) {
            float4 av = *(float4*)&As[k][ty * 4];
            float4 b0 = *(float4*)&Bs[k][tx * 8];
            float4 b1 = *(float4*)&Bs[k][tx * 8 + 4];
            float a[4] = {av.x, av.y, av.z, av.w};
            float b[8] = {b0.x, b0.y, b0.z, b0.w, b1.x, b1.y, b1.z, b1.w};
            #pragma unroll
            for (int i = 0; i < 4; i++)
                #pragma unroll
                for (int j = 0; j < 8; j++)
                    acc[i][j] += a[i] * b[j];
        }
        __syncthreads();
    }

    // epilogue
    float bv[8];
    if (bias) {
        float4 t0 = *(const float4*)&bias[tx * 8];
        float4 t1 = *(const float4*)&bias[tx * 8 + 4];
        bv[0] = t0.x; bv[1] = t0.y; bv[2] = t0.z; bv[3] = t0.w;
        bv[4] = t1.x; bv[5] = t1.y; bv[6] = t1.z; bv[7] = t1.w;
    } else {
        #pragma unroll
        for (int j = 0; j < 8; j++) bv[j] = 0.f;
    }

    #pragma unroll
    for (int i = 0; i < 4; i++) {
        int r = rowBase + ty * 4 + i;
        if (r < M) {
            float* cp = &C[(size_t)r * ldc + coloff + tx * 8];
            float o[8];
            #pragma unroll
            for (int j = 0; j < 8; j++) o[j] = acc[i][j] + bv[j];
            if (ACCUM) {
                float4 e0 = *(float4*)cp;
                float4 e1 = *(float4*)(cp + 4);
                o[0] += e0.x; o[1] += e0.y; o[2] += e0.z; o[3] += e0.w;
                o[4] += e1.x; o[5] += e1.y; o[6] += e1.z; o[7] += e1.w;
            }
            if (RELU) {
                #pragma unroll
                for (int j = 0; j < 8; j++) o[j] = fmaxf(o[j], 0.f);
            }
            *(float4*)cp       = make_float4(o[0], o[1], o[2], o[3]);
            *(float4*)(cp + 4) = make_float4(o[4], o[5], o[6], o[7]);
        }
    }
}

// ---------------- mean aggregation: one warp per node ----------------
__global__ void k_agg(const float* __restrict__ X, float* __restrict__ OUT) {
    int w = (blockIdx.x * blockDim.x + threadIdx.x) >> 5;
    int lane = threadIdx.x & 31;
    if (w >= Nn) return;
    int s = g_rowstart[w], e = g_rowstart[w + 1];
    float4 acc = make_float4(0.f, 0.f, 0.f, 0.f);
    for (int i = s; i < e; i++) {
        int src = g_csr[i];
        float4 v = *(const float4*)&X[(size_t)src * Hd + lane * 4];
        acc.x += v.x; acc.y += v.y; acc.z += v.z; acc.w += v.w;
    }
    float inv = g_invdeg[w];
    acc.x *= inv; acc.y *= inv; acc.z *= inv; acc.w *= inv;
    *(float4*)&OUT[(size_t)w * Hd + lane * 4] = acc;
}

// ---------------- sage2: out[n,c] = agg@Wl2^T + bl2 + x2@Wr2^T ----------------
__global__ void k_final(const float* __restrict__ aggp, const float* __restrict__ x2p,
                        const float* __restrict__ Wl2, const float* __restrict__ bl2,
                        const float* __restrict__ Wr2, float* __restrict__ out) {
    int w = (blockIdx.x * blockDim.x + threadIdx.x) >> 5;
    int lane = threadIdx.x & 31;
    if (w >= Nn) return;
    float4 a = *(const float4*)&aggp[(size_t)w * Hd + lane * 4];
    float4 x = *(const float4*)&x2p[(size_t)w * Hd + lane * 4];
    float res[4];
    #pragma unroll
    for (int c = 0; c < 4; c++) {
        float4 wl = *(const float4*)&Wl2[c * Hd + lane * 4];
        float4 wr = *(const float4*)&Wr2[c * Hd + lane * 4];
        float p = a.x * wl.x + a.y * wl.y + a.z * wl.z + a.w * wl.w
                + x.x * wr.x + x.y * wr.y + x.z * wr.z + x.w * wr.w;
        #pragma unroll
        for (int off = 16; off >= 1; off >>= 1)
            p += __shfl_xor_sync(0xFFFFFFFFu, p, off);
        res[c] = p;
    }
    if (lane < 4) out[(size_t)w * 4 + lane] = res[lane] + bl2[lane];
}

// ---------------- launch ----------------
extern "C" void kernel_launch(void* const* d_in, const int* in_sizes, int n_in,
                              void* d_out, int out_size)
{
    // --- resolve REAL device addresses of scratch symbols (host shadow is invalid!) ---
    void* p;
    float *xcat, *x1, *x2, *aggbuf;
    cudaGetSymbolAddress(&p, g_xcat); xcat = (float*)p; aggbuf = (float*)p;  // alias
    cudaGetSymbolAddress(&p, g_x1);   x1 = (float*)p;
    cudaGetSymbolAddress(&p, g_x2);   x2 = (float*)p;

    // --- input mapping: size-based (elements or bytes), positional fallback ---
    const float *cand0 = nullptr, *cand1 = nullptr;   // {clinical, edge_index} pair
    const float *mel = nullptr;
    const float *Wm = nullptr, *bm = nullptr, *Wc = nullptr, *bc = nullptr;
    const float *Wl1 = nullptr, *bl1 = nullptr, *Wr1 = nullptr;
    const float *Wl2 = nullptr, *bl2 = nullptr, *Wr2 = nullptr;

    bool have128M = false, have512M = false;
    for (int i = 0; i < n_in; i++) {
        long long s = in_sizes[i];
        if (s == 128000000LL) have128M = true;
        if (s == 512000000LL) have512M = true;
    }
    long long div = have128M ? 1 : (have512M ? 4 : 0);

    if (div) {
        for (int i = 0; i < n_in; i++) {
            long long s = in_sizes[i] / div;
            const void* q = d_in[i];
            if (s == 128000000LL)    { mel = (const float*)q; }
            else if (s == 6400000LL) { if (!cand0) cand0 = (const float*)q; else cand1 = (const float*)q; }
            else if (s == 163840LL)  { Wm = (const float*)q; }
            else if (s == 24576LL)   { Wc = (const float*)q; }
            else if (s == 16384LL)   { if (!Wl1) Wl1 = (const float*)q; else Wr1 = (const float*)q; }
            else if (s == 512LL)     { if (!Wl2) Wl2 = (const float*)q; else Wr2 = (const float*)q; }
            else if (s == 128LL)     { if (!bm) bm = (const float*)q; else if (!bc) bc = (const float*)q; else bl1 = (const float*)q; }
            else if (s == 4LL)       { bl2 = (const float*)q; }
        }
    }
    if (!mel || !Wm || !Wc || !Wl1 || !Wr1 || !Wl2 || !Wr2 ||
        !bm || !bc || !bl1 || !bl2 || !cand0 || !cand1) {
        // positional fallback: setup_inputs() insertion order
        cand0 = (const float*)d_in[0];       // clinical
        mel   = (const float*)d_in[1];
        cand1 = (const float*)d_in[2];       // edge_index
        Wm  = (const float*)d_in[3];  bm  = (const float*)d_in[4];
        Wc  = (const float*)d_in[5];  bc  = (const float*)d_in[6];
        Wl1 = (const float*)d_in[7];  bl1 = (const float*)d_in[8];
        Wr1 = (const float*)d_in[9];
        Wl2 = (const float*)d_in[10]; bl2 = (const float*)d_in[11];
        Wr2 = (const float*)d_in[12];
    }
    float* out = (float*)d_out;

    const int NB = (Nn + 1023) / 1024;          // 98
    const int EB = (Ee + 255) / 256;            // 12500
    const int GEMM_BLKS = (Nn + 63) / 64;       // 1563
    const int WARP_BLKS = (Nn + 7) / 8;         // 12500 (8 warps/block)

    // sniff which 6.4M input is the int edge_index
    k_sniff<<<1, 256>>>((const int*)cand0);

    // graph preprocessing (CSR built once, used by both SAGE layers)
    k_zerodeg<<<NB, 1024>>>();
    k_degree<<<EB, 256>>>((const int*)cand0, (const int*)cand1);
    k_scan1<<<NB, 1024>>>();
    k_scan2<<<1, 32>>>(NB);
    k_scan3<<<NB, 1024>>>();
    k_fill<<<EB, 256>>>((const int*)cand0, (const int*)cand1);

    // feature pipeline
    k_copyclin<<<(Nn * 16 + 255) / 256, 256>>>(cand0, cand1);
    // mel_h = relu(mel @ Wm^T + bm) -> xcat cols 64..191
    k_gemm<true, false><<<GEMM_BLKS, 256>>>(mel, MELD, MELD, Wm, bm, xcat, XCATD, CLIND, Nn);
    // x1 = relu(xcat @ Wc^T + bc)
    k_gemm<true, false><<<GEMM_BLKS, 256>>>(xcat, XCATD, XCATD, Wc, bc, x1, Hd, 0, Nn);

    // sage1 (xcat is dead now; reuse as agg buffer)
    k_agg<<<WARP_BLKS, 256>>>(x1, aggbuf);
    k_gemm<false, false><<<GEMM_BLKS, 256>>>(aggbuf, Hd, Hd, Wl1, bl1, x2, Hd, 0, Nn);
    k_gemm<true,  true ><<<GEMM_BLKS, 256>>>(x1, Hd, Hd, Wr1, nullptr, x2, Hd, 0, Nn);

    // sage2
    k_agg<<<WARP_BLKS, 256>>>(x2, aggbuf);
    k_final<<<WARP_BLKS, 256>>>(aggbuf, x2, Wl2, bl2, Wr2, out);
}

// round 10
// speedup vs baseline: 3.5822x; 3.5822x over previous
#include <cuda_runtime.h>
#include <cuda_fp16.h>
#include <cstdint>

#define Nn 100000
#define Ee 3200000
#define CLIND 64
#define MELD 1280
#define Hd 128
#define Cd 4
#define XCATD 192

// ---------------- scratch (device globals; no allocation) ----------------
__device__ float g_melh[(size_t)Nn * Hd];
__device__ float g_x1[(size_t)Nn * Hd];
__device__ float g_x2[(size_t)Nn * Hd];
__device__ float g_agg[(size_t)Nn * Hd];
__device__ int   g_deg[Nn];
__device__ int   g_rowstart[Nn + 1];
__device__ int   g_cursor[Nn];
__device__ int   g_csr[Ee];
__device__ float g_invdeg[Nn];
__device__ int   g_part[128];
__device__ int   g_edge_first;   // 1 if candidate-0 of the 6.4M pair is edge_index

// ---------------- sniff which 6.4M input is edge_index ----------------
__global__ void k_sniff(const int* __restrict__ c0) {
    __shared__ int ok;
    if (threadIdx.x == 0) ok = 1;
    __syncthreads();
    for (int i = threadIdx.x; i < 4096; i += blockDim.x) {
        unsigned v = (unsigned)c0[i];
        if (v >= (unsigned)Nn) ok = 0;
    }
    __syncthreads();
    if (threadIdx.x == 0) g_edge_first = ok;
}

// ---------------- graph preprocessing ----------------
__global__ void k_zerodeg() {
    int i = blockIdx.x * blockDim.x + threadIdx.x;
    if (i < Nn) g_deg[i] = 0;
}
__global__ void k_degree(const int* __restrict__ c0, const int* __restrict__ c1) {
    const int* ei = g_edge_first ? c0 : c1;
    int e = blockIdx.x * blockDim.x + threadIdx.x;
    if (e < Ee) {
        unsigned dst = (unsigned)ei[Ee + e];
        if (dst < (unsigned)Nn) atomicAdd(&g_deg[dst], 1);
    }
}
__global__ void k_scan1() {
    __shared__ int s[1024];
    int i = blockIdx.x * 1024 + threadIdx.x;
    int v = (i < Nn) ? g_deg[i] : 0;
    s[threadIdx.x] = v;
    __syncthreads();
    #pragma unroll
    for (int off = 1; off < 1024; off <<= 1) {
        int t = (threadIdx.x >= off) ? s[threadIdx.x - off] : 0;
        __syncthreads();
        s[threadIdx.x] += t;
        __syncthreads();
    }
    if (i < Nn) g_rowstart[i] = s[threadIdx.x] - v;
    if (threadIdx.x == 1023) g_part[blockIdx.x] = s[1023];
}
__global__ void k_scan2(int nb) {
    if (blockIdx.x == 0 && threadIdx.x == 0) {
        int acc = 0;
        for (int b = 0; b < nb; b++) { int t = g_part[b]; g_part[b] = acc; acc += t; }
        g_rowstart[Nn] = acc;
    }
}
__global__ void k_scan3() {
    int i = blockIdx.x * 1024 + threadIdx.x;
    if (i < Nn) {
        g_rowstart[i] += g_part[blockIdx.x];
        g_cursor[i] = 0;
        int d = g_deg[i];
        g_invdeg[i] = 1.0f / (float)(d > 1 ? d : 1);
    }
}
__global__ void k_fill(const int* __restrict__ c0, const int* __restrict__ c1) {
    const int* ei = g_edge_first ? c0 : c1;
    int e = blockIdx.x * blockDim.x + threadIdx.x;
    if (e < Ee) {
        unsigned dst = (unsigned)ei[Ee + e];
        unsigned src = (unsigned)ei[e];
        if (dst < (unsigned)Nn) {
            int pos = atomicAdd(&g_cursor[dst], 1);
            int idx = g_rowstart[dst] + pos;
            if (idx >= 0 && idx < Ee)
                g_csr[idx] = (src < (unsigned)Nn) ? (int)src : 0;
        }
    }
}

// ---------------- HMMA fp16 dual-segment GEMM ----------------
// C[row, 0:128] = act( A0[row,:kc0*64] @ W0^T + A1[row,:kc1*64] @ W1^T + bias )
// Block: 128 rows x 128 cols, 8 warps, warp tile 32x64. K-chunks of 64.
// fp32 -> fp16 conversion fused; smem fp16 tiles SW128-swizzled for ldmatrix.

__device__ __forceinline__ uint32_t smem_u32(const void* p) {
    uint32_t a;
    asm("{ .reg .u64 t; cvta.to.shared.u64 t, %1; cvt.u32.u64 %0, t; }" : "=r"(a) : "l"(p));
    return a;
}

__device__ __forceinline__ void ldsm4(uint32_t* r, uint32_t addr) {
    asm volatile("ldmatrix.sync.aligned.m8n8.x4.shared.b16 {%0,%1,%2,%3}, [%4];"
                 : "=r"(r[0]), "=r"(r[1]), "=r"(r[2]), "=r"(r[3]) : "r"(addr));
}

__device__ __forceinline__ void mma16816(float* c, const uint32_t* a, uint32_t b0, uint32_t b1) {
    asm volatile(
        "mma.sync.aligned.m16n8k16.row.col.f32.f16.f16.f32 "
        "{%0,%1,%2,%3}, {%4,%5,%6,%7}, {%8,%9}, {%0,%1,%2,%3};"
        : "+f"(c[0]), "+f"(c[1]), "+f"(c[2]), "+f"(c[3])
        : "r"(a[0]), "r"(a[1]), "r"(a[2]), "r"(a[3]), "r"(b0), "r"(b1));
}

__device__ __forceinline__ uint4 cvt8h(const float* f) {
    uint32_t u[4];
    #pragma unroll
    for (int i = 0; i < 4; i++) {
        __half2 h = __floats2half2_rn(f[2 * i], f[2 * i + 1]);
        u[i] = *(uint32_t*)&h;
    }
    return make_uint4(u[0], u[1], u[2], u[3]);
}

__global__ void __launch_bounds__(256, 2) k_mm(
    const float* __restrict__ A0a, const float* __restrict__ A0b, int lda0,
    const float* __restrict__ W0, int ldw0, int kc0,
    const float* __restrict__ A1, int lda1,
    const float* __restrict__ W1, int ldw1, int kc1,
    const float* __restrict__ bias, float* __restrict__ C,
    int doRelu, int M)
{
    __shared__ __align__(16) char sA[16384];   // 128 rows x 64 halves, SW128
    __shared__ __align__(16) char sB[16384];   // 128 n    x 64 halves, SW128
    const uint32_t sAu = smem_u32(sA);
    const uint32_t sBu = smem_u32(sB);
    int tid = threadIdx.x;
    int lane = tid & 31, wid = tid >> 5;
    int warpM = wid & 3, warpN = wid >> 2;     // 4 x 2 warp grid
    int rowBase = blockIdx.x * 128;
    const float* A0 = g_edge_first ? A0b : A0a;

    float acc[2][8][4];
    #pragma unroll
    for (int mt = 0; mt < 2; mt++)
        #pragma unroll
        for (int nt = 0; nt < 8; nt++)
            #pragma unroll
            for (int j = 0; j < 4; j++) acc[mt][nt][j] = 0.f;

    // precompute per-lane ldmatrix smem addresses (kb-invariant parts)
    // A: row = warpM*32 + mt*16 + (lane&15); colb = kb*32 + ((lane>>4)&1)*16
    // B: n   = warpN*64 + ng*16 + ((lane>>4)<<3) + (lane&7); colb = kb*32 + ((lane>>3)&1)*16
    const int aRow[2] = { warpM * 32 + (lane & 15), warpM * 32 + 16 + (lane & 15) };
    const int aColb = ((lane >> 4) & 1) * 16;
    const int bNbase = warpN * 64 + ((lane >> 4) << 3) + (lane & 7);
    const int bColb = ((lane >> 3) & 1) * 16;

    for (int seg = 0; seg < 2; seg++) {
        const float* A = seg ? A1 : A0;
        const float* W = seg ? W1 : W0;
        const int lda = seg ? lda1 : lda0;
        const int ldw = seg ? ldw1 : ldw0;
        const int kc  = seg ? kc1 : kc0;
        for (int c = 0; c < kc; c++) {
            const int k0 = c * 64;
            // ---- convert fp32 -> fp16 into smem ----
            #pragma unroll
            for (int it = 0; it < 4; it++) {
                int g = tid + it * 256;
                int r = g >> 3, cq = (g & 7) * 8;
                int rg = rowBase + r; if (rg > M - 1) rg = M - 1;
                const float* ap = A + (size_t)rg * lda + k0 + cq;
                float4 v0 = *(const float4*)ap;
                float4 v1 = *(const float4*)(ap + 4);
                float fa[8] = {v0.x, v0.y, v0.z, v0.w, v1.x, v1.y, v1.z, v1.w};
                uint32_t off = r * 128 + cq * 2;
                uint32_t sw = off ^ ((off >> 3) & 0x70);
                *(uint4*)(sA + sw) = cvt8h(fa);

                const float* wp = W + (size_t)r * ldw + k0 + cq;
                float4 w0 = *(const float4*)wp;
                float4 w1 = *(const float4*)(wp + 4);
                float fb[8] = {w0.x, w0.y, w0.z, w0.w, w1.x, w1.y, w1.z, w1.w};
                *(uint4*)(sB + sw) = cvt8h(fb);
            }
            __syncthreads();
            // ---- HMMA compute on the 64-wide chunk ----
            #pragma unroll
            for (int kb = 0; kb < 4; kb++) {
                uint32_t a[2][4];
                #pragma unroll
                for (int mt = 0; mt < 2; mt++) {
                    uint32_t off = aRow[mt] * 128 + kb * 32 + aColb;
                    off ^= (off >> 3) & 0x70;
                    ldsm4(a[mt], sAu + off);
                }
                uint32_t b[4][4];
                #pragma unroll
                for (int ng = 0; ng < 4; ng++) {
                    uint32_t off = (bNbase + ng * 16) * 128 + kb * 32 + bColb;
                    off ^= (off >> 3) & 0x70;
                    ldsm4(b[ng], sBu + off);
                }
                #pragma unroll
                for (int mt = 0; mt < 2; mt++)
                    #pragma unroll
                    for (int nt = 0; nt < 8; nt++)
                        mma16816(acc[mt][nt], a[mt], b[nt >> 1][(nt & 1) * 2], b[nt >> 1][(nt & 1) * 2 + 1]);
            }
            __syncthreads();
        }
    }

    // ---- epilogue: bias + relu + store ----
    #pragma unroll
    for (int mt = 0; mt < 2; mt++) {
        int r0 = rowBase + warpM * 32 + mt * 16 + (lane >> 2);
        int r1 = r0 + 8;
        #pragma unroll
        for (int nt = 0; nt < 8; nt++) {
            int col = warpN * 64 + nt * 8 + (lane & 3) * 2;
            float b0 = bias[col], b1 = bias[col + 1];
            float v0 = acc[mt][nt][0] + b0, v1 = acc[mt][nt][1] + b1;
            float v2 = acc[mt][nt][2] + b0, v3 = acc[mt][nt][3] + b1;
            if (doRelu) {
                v0 = fmaxf(v0, 0.f); v1 = fmaxf(v1, 0.f);
                v2 = fmaxf(v2, 0.f); v3 = fmaxf(v3, 0.f);
            }
            if (r0 < M) *(float2*)&C[(size_t)r0 * Hd + col] = make_float2(v0, v1);
            if (r1 < M) *(float2*)&C[(size_t)r1 * Hd + col] = make_float2(v2, v3);
        }
    }
}

// ---------------- mean aggregation: one warp per node ----------------
__global__ void k_agg(const float* __restrict__ X, float* __restrict__ OUT) {
    int w = (blockIdx.x * blockDim.x + threadIdx.x) >> 5;
    int lane = threadIdx.x & 31;
    if (w >= Nn) return;
    int s = g_rowstart[w], e = g_rowstart[w + 1];
    float4 acc = make_float4(0.f, 0.f, 0.f, 0.f);
    for (int i = s; i < e; i++) {
        int src = g_csr[i];
        float4 v = *(const float4*)&X[(size_t)src * Hd + lane * 4];
        acc.x += v.x; acc.y += v.y; acc.z += v.z; acc.w += v.w;
    }
    float inv = g_invdeg[w];
    acc.x *= inv; acc.y *= inv; acc.z *= inv; acc.w *= inv;
    *(float4*)&OUT[(size_t)w * Hd + lane * 4] = acc;
}

// ---------------- sage2: out[n,c] = agg@Wl2^T + bl2 + x2@Wr2^T ----------------
__global__ void k_final(const float* __restrict__ aggp, const float* __restrict__ x2p,
                        const float* __restrict__ Wl2, const float* __restrict__ bl2,
                        const float* __restrict__ Wr2, float* __restrict__ out) {
    int w = (blockIdx.x * blockDim.x + threadIdx.x) >> 5;
    int lane = threadIdx.x & 31;
    if (w >= Nn) return;
    float4 a = *(const float4*)&aggp[(size_t)w * Hd + lane * 4];
    float4 x = *(const float4*)&x2p[(size_t)w * Hd + lane * 4];
    float res[4];
    #pragma unroll
    for (int c = 0; c < 4; c++) {
        float4 wl = *(const float4*)&Wl2[c * Hd + lane * 4];
        float4 wr = *(const float4*)&Wr2[c * Hd + lane * 4];
        float p = a.x * wl.x + a.y * wl.y + a.z * wl.z + a.w * wl.w
                + x.x * wr.x + x.y * wr.y + x.z * wr.z + x.w * wr.w;
        #pragma unroll
        for (int off = 16; off >= 1; off >>= 1)
            p += __shfl_xor_sync(0xFFFFFFFFu, p, off);
        res[c] = p;
    }
    if (lane < 4) out[(size_t)w * 4 + lane] = res[lane] + bl2[lane];
}

// ---------------- launch ----------------
extern "C" void kernel_launch(void* const* d_in, const int* in_sizes, int n_in,
                              void* d_out, int out_size)
{
    void* p;
    float *melh, *x1, *x2, *aggbuf;
    cudaGetSymbolAddress(&p, g_melh); melh = (float*)p;
    cudaGetSymbolAddress(&p, g_x1);   x1 = (float*)p;
    cudaGetSymbolAddress(&p, g_x2);   x2 = (float*)p;
    cudaGetSymbolAddress(&p, g_agg);  aggbuf = (float*)p;

    const float *cand0 = nullptr, *cand1 = nullptr;
    const float *mel = nullptr;
    const float *Wm = nullptr, *bm = nullptr, *Wc = nullptr, *bc = nullptr;
    const float *Wl1 = nullptr, *bl1 = nullptr, *Wr1 = nullptr;
    const float *Wl2 = nullptr, *bl2 = nullptr, *Wr2 = nullptr;

    bool have128M = false, have512M = false;
    for (int i = 0; i < n_in; i++) {
        long long s = in_sizes[i];
        if (s == 128000000LL) have128M = true;
        if (s == 512000000LL) have512M = true;
    }
    long long div = have128M ? 1 : (have512M ? 4 : 0);
    if (div) {
        for (int i = 0; i < n_in; i++) {
            long long s = in_sizes[i] / div;
            const void* q = d_in[i];
            if (s == 128000000LL)    { mel = (const float*)q; }
            else if (s == 6400000LL) { if (!cand0) cand0 = (const float*)q; else cand1 = (const float*)q; }
            else if (s == 163840LL)  { Wm = (const float*)q; }
            else if (s == 24576LL)   { Wc = (const float*)q; }
            else if (s == 16384LL)   { if (!Wl1) Wl1 = (const float*)q; else Wr1 = (const float*)q; }
            else if (s == 512LL)     { if (!Wl2) Wl2 = (const float*)q; else Wr2 = (const float*)q; }
            else if (s == 128LL)     { if (!bm) bm = (const float*)q; else if (!bc) bc = (const float*)q; else bl1 = (const float*)q; }
            else if (s == 4LL)       { bl2 = (const float*)q; }
        }
    }
    if (!mel || !Wm || !Wc || !Wl1 || !Wr1 || !Wl2 || !Wr2 ||
        !bm || !bc || !bl1 || !bl2 || !cand0 || !cand1) {
        cand0 = (const float*)d_in[0];
        mel   = (const float*)d_in[1];
        cand1 = (const float*)d_in[2];
        Wm  = (const float*)d_in[3];  bm  = (const float*)d_in[4];
        Wc  = (const float*)d_in[5];  bc  = (const float*)d_in[6];
        Wl1 = (const float*)d_in[7];  bl1 = (const float*)d_in[8];
        Wr1 = (const float*)d_in[9];
        Wl2 = (const float*)d_in[10]; bl2 = (const float*)d_in[11];
        Wr2 = (const float*)d_in[12];
    }
    float* out = (float*)d_out;

    const int NB = (Nn + 1023) / 1024;
    const int EB = (Ee + 255) / 256;
    const int MM_BLKS = (Nn + 127) / 128;       // 782
    const int WARP_BLKS = (Nn + 7) / 8;

    k_sniff<<<1, 256>>>((const int*)cand0);

    // graph preprocessing
    k_zerodeg<<<NB, 1024>>>();
    k_degree<<<EB, 256>>>((const int*)cand0, (const int*)cand1);
    k_scan1<<<NB, 1024>>>();
    k_scan2<<<1, 32>>>(NB);
    k_scan3<<<NB, 1024>>>();
    k_fill<<<EB, 256>>>((const int*)cand0, (const int*)cand1);

    // mel_h = relu(mel @ Wm^T + bm)
    k_mm<<<MM_BLKS, 256>>>(mel, mel, MELD, Wm, MELD, MELD / 64,
                           nullptr, 0, nullptr, 0, 0,
                           bm, melh, 1, Nn);
    // x1 = relu(clinical @ Wc[:, :64]^T + mel_h @ Wc[:, 64:]^T + bc)
    k_mm<<<MM_BLKS, 256>>>(cand0, cand1, CLIND, Wc, XCATD, 1,
                           melh, Hd, Wc + CLIND, XCATD, 2,
                           bc, x1, 1, Nn);
    // sage1: x2 = relu(agg @ Wl1^T + x1 @ Wr1^T + bl1)
    k_agg<<<WARP_BLKS, 256>>>(x1, aggbuf);
    k_mm<<<MM_BLKS, 256>>>(aggbuf, aggbuf, Hd, Wl1, Hd, 2,
                           x1, Hd, Wr1, Hd, 2,
                           bl1, x2, 1, Nn);
    // sage2
    k_agg<<<WARP_BLKS, 256>>>(x2, aggbuf);
    k_final<<<WARP_BLKS, 256>>>(aggbuf, x2, Wl2, bl2, Wr2, out);
}

// round 11
// speedup vs baseline: 4.3199x; 1.2059x over previous
#include <cuda_runtime.h>
#include <cuda_fp16.h>
#include <cstdint>

#define Nn 100000
#define Ee 3200000
#define CLIND 64
#define MELD 1280
#define Hd 128
#define Cd 4
#define XCATD 192

// ---------------- scratch (device globals; no allocation) ----------------
__device__ __half g_melh[(size_t)Nn * Hd];
__device__ __half g_x1[(size_t)Nn * Hd];
__device__ __half g_x2[(size_t)Nn * Hd];
__device__ __half g_aggh[(size_t)Nn * Hd];    // layer-1 aggregate (fp16)
__device__ float  g_aggf[(size_t)Nn * Hd];    // layer-2 aggregate (fp32)
__device__ __half g_wm[(size_t)Hd * MELD];    // fp16 weights
__device__ __half g_wc[(size_t)Hd * XCATD];
__device__ __half g_wl1[(size_t)Hd * Hd];
__device__ __half g_wr1[(size_t)Hd * Hd];
__device__ int   g_deg[Nn];
__device__ int   g_rowstart[Nn + 1];
__device__ int   g_cursor[Nn];
__device__ int   g_csr[Ee];
__device__ float g_invdeg[Nn];
__device__ int   g_part[128];
__device__ int   g_edge_first;

// ---------------- sniff which 6.4M input is edge_index ----------------
__global__ void k_sniff(const int* __restrict__ c0) {
    __shared__ int ok;
    if (threadIdx.x == 0) ok = 1;
    __syncthreads();
    for (int i = threadIdx.x; i < 4096; i += blockDim.x) {
        unsigned v = (unsigned)c0[i];
        if (v >= (unsigned)Nn) ok = 0;
    }
    __syncthreads();
    if (threadIdx.x == 0) g_edge_first = ok;
}

// ---------------- weight fp32 -> fp16 ----------------
__global__ void k_cvtw(const float* __restrict__ src, __half* __restrict__ dst, int n) {
    int i = blockIdx.x * blockDim.x + threadIdx.x;
    if (i * 4 < n) {
        float4 v = *(const float4*)&src[i * 4];
        __half2 h0 = __floats2half2_rn(v.x, v.y);
        __half2 h1 = __floats2half2_rn(v.z, v.w);
        *(uint2*)&dst[i * 4] = make_uint2(*(uint32_t*)&h0, *(uint32_t*)&h1);
    }
}

// ---------------- graph preprocessing ----------------
__global__ void k_zerodeg() {
    int i = blockIdx.x * blockDim.x + threadIdx.x;
    if (i < Nn) g_deg[i] = 0;
}
__global__ void k_degree(const int* __restrict__ c0, const int* __restrict__ c1) {
    const int* ei = g_edge_first ? c0 : c1;
    int e = blockIdx.x * blockDim.x + threadIdx.x;
    if (e < Ee) {
        unsigned dst = (unsigned)ei[Ee + e];
        if (dst < (unsigned)Nn) atomicAdd(&g_deg[dst], 1);
    }
}
__global__ void k_scan1() {
    __shared__ int s[1024];
    int i = blockIdx.x * 1024 + threadIdx.x;
    int v = (i < Nn) ? g_deg[i] : 0;
    s[threadIdx.x] = v;
    __syncthreads();
    #pragma unroll
    for (int off = 1; off < 1024; off <<= 1) {
        int t = (threadIdx.x >= off) ? s[threadIdx.x - off] : 0;
        __syncthreads();
        s[threadIdx.x] += t;
        __syncthreads();
    }
    if (i < Nn) g_rowstart[i] = s[threadIdx.x] - v;
    if (threadIdx.x == 1023) g_part[blockIdx.x] = s[1023];
}
__global__ void k_scan2(int nb) {
    if (blockIdx.x == 0 && threadIdx.x == 0) {
        int acc = 0;
        for (int b = 0; b < nb; b++) { int t = g_part[b]; g_part[b] = acc; acc += t; }
        g_rowstart[Nn] = acc;
    }
}
__global__ void k_scan3() {
    int i = blockIdx.x * 1024 + threadIdx.x;
    if (i < Nn) {
        g_rowstart[i] += g_part[blockIdx.x];
        g_cursor[i] = 0;
        int d = g_deg[i];
        g_invdeg[i] = 1.0f / (float)(d > 1 ? d : 1);
    }
}
__global__ void k_fill(const int* __restrict__ c0, const int* __restrict__ c1) {
    const int* ei = g_edge_first ? c0 : c1;
    int e = blockIdx.x * blockDim.x + threadIdx.x;
    if (e < Ee) {
        unsigned dst = (unsigned)ei[Ee + e];
        unsigned src = (unsigned)ei[e];
        if (dst < (unsigned)Nn) {
            int pos = atomicAdd(&g_cursor[dst], 1);
            int idx = g_rowstart[dst] + pos;
            if (idx >= 0 && idx < Ee)
                g_csr[idx] = (src < (unsigned)Nn) ? (int)src : 0;
        }
    }
}

// ---------------- HMMA fp16 dual-segment GEMM ----------------
// C(half)[row,0:128] = act( A0 @ W0^T + A1 @ W1^T + bias(f32) )
// A inputs fp32 (converted) or fp16 (copied); W pre-converted fp16.
__device__ __forceinline__ uint32_t smem_u32(const void* p) {
    uint32_t a;
    asm("{ .reg .u64 t; cvta.to.shared.u64 t, %1; cvt.u32.u64 %0, t; }" : "=r"(a) : "l"(p));
    return a;
}
__device__ __forceinline__ void ldsm4(uint32_t* r, uint32_t addr) {
    asm volatile("ldmatrix.sync.aligned.m8n8.x4.shared.b16 {%0,%1,%2,%3}, [%4];"
                 : "=r"(r[0]), "=r"(r[1]), "=r"(r[2]), "=r"(r[3]) : "r"(addr));
}
__device__ __forceinline__ void mma16816(float* c, const uint32_t* a, uint32_t b0, uint32_t b1) {
    asm volatile(
        "mma.sync.aligned.m16n8k16.row.col.f32.f16.f16.f32 "
        "{%0,%1,%2,%3}, {%4,%5,%6,%7}, {%8,%9}, {%0,%1,%2,%3};"
        : "+f"(c[0]), "+f"(c[1]), "+f"(c[2]), "+f"(c[3])
        : "r"(a[0]), "r"(a[1]), "r"(a[2]), "r"(a[3]), "r"(b0), "r"(b1));
}
__device__ __forceinline__ uint4 cvt8h(const float* f) {
    uint32_t u[4];
    #pragma unroll
    for (int i = 0; i < 4; i++) {
        __half2 h = __floats2half2_rn(f[2 * i], f[2 * i + 1]);
        u[i] = *(uint32_t*)&h;
    }
    return make_uint4(u[0], u[1], u[2], u[3]);
}

template <bool A0H, bool A1H>
__global__ void __launch_bounds__(256, 2) k_mm(
    const void* __restrict__ A0a, const void* __restrict__ A0b, int lda0,
    const __half* __restrict__ W0, int ldw0, int kc0,
    const void* __restrict__ A1, int lda1,
    const __half* __restrict__ W1, int ldw1, int kc1,
    const float* __restrict__ bias, __half* __restrict__ C,
    int doRelu, int M)
{
    __shared__ __align__(16) char sA[16384];   // 128 rows x 64 halves, SW128
    __shared__ __align__(16) char sB[16384];
    const uint32_t sAu = smem_u32(sA);
    const uint32_t sBu = smem_u32(sB);
    int tid = threadIdx.x;
    int lane = tid & 31, wid = tid >> 5;
    int warpM = wid & 3, warpN = wid >> 2;
    int rowBase = blockIdx.x * 128;
    const void* A0 = g_edge_first ? A0b : A0a;

    float acc[2][8][4];
    #pragma unroll
    for (int mt = 0; mt < 2; mt++)
        #pragma unroll
        for (int nt = 0; nt < 8; nt++)
            #pragma unroll
            for (int j = 0; j < 4; j++) acc[mt][nt][j] = 0.f;

    const int aRow[2] = { warpM * 32 + (lane & 15), warpM * 32 + 16 + (lane & 15) };
    const int aColb = ((lane >> 4) & 1) * 16;
    const int bNbase = warpN * 64 + ((lane >> 4) << 3) + (lane & 7);
    const int bColb = ((lane >> 3) & 1) * 16;

    for (int seg = 0; seg < 2; seg++) {
        const void* A = seg ? A1 : A0;
        const __half* W = seg ? W1 : W0;
        const int lda = seg ? lda1 : lda0;
        const int ldw = seg ? ldw1 : ldw0;
        const int kc  = seg ? kc1 : kc0;
        const bool ah = seg ? A1H : A0H;
        for (int c = 0; c < kc; c++) {
            const int k0 = c * 64;
            #pragma unroll
            for (int it = 0; it < 4; it++) {
                int g = tid + it * 256;
                int r = g >> 3, cq = (g & 7) * 8;
                int rg = rowBase + r; if (rg > M - 1) rg = M - 1;
                uint32_t off = r * 128 + cq * 2;
                uint32_t sw = off ^ ((off >> 3) & 0x70);
                if (ah) {
                    const __half* ap = (const __half*)A + (size_t)rg * lda + k0 + cq;
                    *(uint4*)(sA + sw) = *(const uint4*)ap;
                } else {
                    const float* ap = (const float*)A + (size_t)rg * lda + k0 + cq;
                    float4 v0 = *(const float4*)ap;
                    float4 v1 = *(const float4*)(ap + 4);
                    float fa[8] = {v0.x, v0.y, v0.z, v0.w, v1.x, v1.y, v1.z, v1.w};
                    *(uint4*)(sA + sw) = cvt8h(fa);
                }
                const __half* wp = W + (size_t)r * ldw + k0 + cq;
                *(uint4*)(sB + sw) = *(const uint4*)wp;
            }
            __syncthreads();
            #pragma unroll
            for (int kb = 0; kb < 4; kb++) {
                uint32_t a[2][4];
                #pragma unroll
                for (int mt = 0; mt < 2; mt++) {
                    uint32_t off = aRow[mt] * 128 + kb * 32 + aColb;
                    off ^= (off >> 3) & 0x70;
                    ldsm4(a[mt], sAu + off);
                }
                uint32_t b[4][4];
                #pragma unroll
                for (int ng = 0; ng < 4; ng++) {
                    uint32_t off = (bNbase + ng * 16) * 128 + kb * 32 + bColb;
                    off ^= (off >> 3) & 0x70;
                    ldsm4(b[ng], sBu + off);
                }
                #pragma unroll
                for (int mt = 0; mt < 2; mt++)
                    #pragma unroll
                    for (int nt = 0; nt < 8; nt++)
                        mma16816(acc[mt][nt], a[mt], b[nt >> 1][(nt & 1) * 2], b[nt >> 1][(nt & 1) * 2 + 1]);
            }
            __syncthreads();
        }
    }

    #pragma unroll
    for (int mt = 0; mt < 2; mt++) {
        int r0 = rowBase + warpM * 32 + mt * 16 + (lane >> 2);
        int r1 = r0 + 8;
        #pragma unroll
        for (int nt = 0; nt < 8; nt++) {
            int col = warpN * 64 + nt * 8 + (lane & 3) * 2;
            float b0 = bias[col], b1 = bias[col + 1];
            float v0 = acc[mt][nt][0] + b0, v1 = acc[mt][nt][1] + b1;
            float v2 = acc[mt][nt][2] + b0, v3 = acc[mt][nt][3] + b1;
            if (doRelu) {
                v0 = fmaxf(v0, 0.f); v1 = fmaxf(v1, 0.f);
                v2 = fmaxf(v2, 0.f); v3 = fmaxf(v3, 0.f);
            }
            __half2 h0 = __floats2half2_rn(v0, v1);
            __half2 h1 = __floats2half2_rn(v2, v3);
            if (r0 < M) *(__half2*)&C[(size_t)r0 * Hd + col] = h0;
            if (r1 < M) *(__half2*)&C[(size_t)r1 * Hd + col] = h1;
        }
    }
}

// ---------------- mean aggregation: one warp per node, fp16 gather ----------------
template <bool OUTH>
__global__ void k_agg(const __half* __restrict__ X, void* __restrict__ OUT) {
    int w = (blockIdx.x * blockDim.x + threadIdx.x) >> 5;
    int lane = threadIdx.x & 31;
    if (w >= Nn) return;
    int s = g_rowstart[w], e = g_rowstart[w + 1];
    float a0 = 0.f, a1 = 0.f, a2 = 0.f, a3 = 0.f;
    int i = s;
    for (; i + 1 < e; i += 2) {
        int s0 = g_csr[i], s1 = g_csr[i + 1];
        uint2 u0 = *(const uint2*)&X[(size_t)s0 * Hd + lane * 4];
        uint2 u1 = *(const uint2*)&X[(size_t)s1 * Hd + lane * 4];
        float2 f0 = __half22float2(*(__half2*)&u0.x);
        float2 f1 = __half22float2(*(__half2*)&u0.y);
        float2 f2 = __half22float2(*(__half2*)&u1.x);
        float2 f3 = __half22float2(*(__half2*)&u1.y);
        a0 += f0.x + f2.x; a1 += f0.y + f2.y;
        a2 += f1.x + f3.x; a3 += f1.y + f3.y;
    }
    if (i < e) {
        int s0 = g_csr[i];
        uint2 u0 = *(const uint2*)&X[(size_t)s0 * Hd + lane * 4];
        float2 f0 = __half22float2(*(__half2*)&u0.x);
        float2 f1 = __half22float2(*(__half2*)&u0.y);
        a0 += f0.x; a1 += f0.y; a2 += f1.x; a3 += f1.y;
    }
    float inv = g_invdeg[w];
    a0 *= inv; a1 *= inv; a2 *= inv; a3 *= inv;
    if (OUTH) {
        __half2 h0 = __floats2half2_rn(a0, a1);
        __half2 h1 = __floats2half2_rn(a2, a3);
        *(uint2*)&((__half*)OUT)[(size_t)w * Hd + lane * 4] =
            make_uint2(*(uint32_t*)&h0, *(uint32_t*)&h1);
    } else {
        *(float4*)&((float*)OUT)[(size_t)w * Hd + lane * 4] = make_float4(a0, a1, a2, a3);
    }
}

// ---------------- sage2: out[n,c] = agg@Wl2^T + bl2 + x2@Wr2^T ----------------
__global__ void k_final(const float* __restrict__ aggp, const __half* __restrict__ x2p,
                        const float* __restrict__ Wl2, const float* __restrict__ bl2,
                        const float* __restrict__ Wr2, float* __restrict__ out) {
    int w = (blockIdx.x * blockDim.x + threadIdx.x) >> 5;
    int lane = threadIdx.x & 31;
    if (w >= Nn) return;
    float4 a = *(const float4*)&aggp[(size_t)w * Hd + lane * 4];
    uint2 u = *(const uint2*)&x2p[(size_t)w * Hd + lane * 4];
    float2 xf0 = __half22float2(*(__half2*)&u.x);
    float2 xf1 = __half22float2(*(__half2*)&u.y);
    float res[4];
    #pragma unroll
    for (int c = 0; c < 4; c++) {
        float4 wl = *(const float4*)&Wl2[c * Hd + lane * 4];
        float4 wr = *(const float4*)&Wr2[c * Hd + lane * 4];
        float p = a.x * wl.x + a.y * wl.y + a.z * wl.z + a.w * wl.w
                + xf0.x * wr.x + xf0.y * wr.y + xf1.x * wr.z + xf1.y * wr.w;
        #pragma unroll
        for (int off = 16; off >= 1; off >>= 1)
            p += __shfl_xor_sync(0xFFFFFFFFu, p, off);
        res[c] = p;
    }
    if (lane < 4) out[(size_t)w * 4 + lane] = res[lane] + bl2[lane];
}

// ---------------- launch ----------------
extern "C" void kernel_launch(void* const* d_in, const int* in_sizes, int n_in,
                              void* d_out, int out_size)
{
    void* p;
    __half *melh, *x1, *x2, *aggh, *wm, *wc, *wl1, *wr1;
    float *aggf;
    cudaGetSymbolAddress(&p, g_melh); melh = (__half*)p;
    cudaGetSymbolAddress(&p, g_x1);   x1 = (__half*)p;
    cudaGetSymbolAddress(&p, g_x2);   x2 = (__half*)p;
    cudaGetSymbolAddress(&p, g_aggh); aggh = (__half*)p;
    cudaGetSymbolAddress(&p, g_aggf); aggf = (float*)p;
    cudaGetSymbolAddress(&p, g_wm);   wm = (__half*)p;
    cudaGetSymbolAddress(&p, g_wc);   wc = (__half*)p;
    cudaGetSymbolAddress(&p, g_wl1);  wl1 = (__half*)p;
    cudaGetSymbolAddress(&p, g_wr1);  wr1 = (__half*)p;

    const float *cand0 = nullptr, *cand1 = nullptr;
    const float *mel = nullptr;
    const float *Wm = nullptr, *bm = nullptr, *Wc = nullptr, *bc = nullptr;
    const float *Wl1 = nullptr, *bl1 = nullptr, *Wr1 = nullptr;
    const float *Wl2 = nullptr, *bl2 = nullptr, *Wr2 = nullptr;

    bool have128M = false, have512M = false;
    for (int i = 0; i < n_in; i++) {
        long long s = in_sizes[i];
        if (s == 128000000LL) have128M = true;
        if (s == 512000000LL) have512M = true;
    }
    long long div = have128M ? 1 : (have512M ? 4 : 0);
    if (div) {
        for (int i = 0; i < n_in; i++) {
            long long s = in_sizes[i] / div;
            const void* q = d_in[i];
            if (s == 128000000LL)    { mel = (const float*)q; }
            else if (s == 6400000LL) { if (!cand0) cand0 = (const float*)q; else cand1 = (const float*)q; }
            else if (s == 163840LL)  { Wm = (const float*)q; }
            else if (s == 24576LL)   { Wc = (const float*)q; }
            else if (s == 16384LL)   { if (!Wl1) Wl1 = (const float*)q; else Wr1 = (const float*)q; }
            else if (s == 512LL)     { if (!Wl2) Wl2 = (const float*)q; else Wr2 = (const float*)q; }
            else if (s == 128LL)     { if (!bm) bm = (const float*)q; else if (!bc) bc = (const float*)q; else bl1 = (const float*)q; }
            else if (s == 4LL)       { bl2 = (const float*)q; }
        }
    }
    if (!mel || !Wm || !Wc || !Wl1 || !Wr1 || !Wl2 || !Wr2 ||
        !bm || !bc || !bl1 || !bl2 || !cand0 || !cand1) {
        cand0 = (const float*)d_in[0];
        mel   = (const float*)d_in[1];
        cand1 = (const float*)d_in[2];
        Wm  = (const float*)d_in[3];  bm  = (const float*)d_in[4];
        Wc  = (const float*)d_in[5];  bc  = (const float*)d_in[6];
        Wl1 = (const float*)d_in[7];  bl1 = (const float*)d_in[8];
        Wr1 = (const float*)d_in[9];
        Wl2 = (const float*)d_in[10]; bl2 = (const float*)d_in[11];
        Wr2 = (const float*)d_in[12];
    }
    float* out = (float*)d_out;

    const int NB = (Nn + 1023) / 1024;
    const int EB = (Ee + 255) / 256;
    const int MM_BLKS = (Nn + 127) / 128;
    const int WARP_BLKS = (Nn + 7) / 8;

    k_sniff<<<1, 256>>>((const int*)cand0);

    // weights -> fp16 (once per call; tiny)
    k_cvtw<<<(163840 / 4 + 255) / 256, 256>>>(Wm, wm, 163840);
    k_cvtw<<<(24576 / 4 + 255) / 256, 256>>>(Wc, wc, 24576);
    k_cvtw<<<(16384 / 4 + 255) / 256, 256>>>(Wl1, wl1, 16384);
    k_cvtw<<<(16384 / 4 + 255) / 256, 256>>>(Wr1, wr1, 16384);

    // graph preprocessing
    k_zerodeg<<<NB, 1024>>>();
    k_degree<<<EB, 256>>>((const int*)cand0, (const int*)cand1);
    k_scan1<<<NB, 1024>>>();
    k_scan2<<<1, 32>>>(NB);
    k_scan3<<<NB, 1024>>>();
    k_fill<<<EB, 256>>>((const int*)cand0, (const int*)cand1);

    // mel_h = relu(mel @ Wm^T + bm)   [A fp32 -> cvt]
    k_mm<false, false><<<MM_BLKS, 256>>>(mel, mel, MELD, wm, MELD, MELD / 64,
                                         nullptr, 0, nullptr, 0, 0,
                                         bm, melh, 1, Nn);
    // x1 = relu(clinical @ Wc[:,:64]^T + mel_h @ Wc[:,64:]^T + bc)
    k_mm<false, true><<<MM_BLKS, 256>>>(cand0, cand1, CLIND, wc, XCATD, 1,
                                        melh, Hd, wc + CLIND, XCATD, 2,
                                        bc, x1, 1, Nn);
    // sage1: x2 = relu(agg @ Wl1^T + x1 @ Wr1^T + bl1)
    k_agg<true><<<WARP_BLKS, 256>>>(x1, aggh);
    k_mm<true, true><<<MM_BLKS, 256>>>(aggh, aggh, Hd, wl1, Hd, 2,
                                       x1, Hd, wr1, Hd, 2,
                                       bl1, x2, 1, Nn);
    // sage2
    k_agg<false><<<WARP_BLKS, 256>>>(x2, aggf);
    k_final<<<WARP_BLKS, 256>>>(aggf, x2, Wl2, bl2, Wr2, out);
}